// round 12
// baseline (speedup 1.0000x reference)
#include <cuda_runtime.h>
#include <cuda_bf16.h>
#include <math.h>

// ============================================================================
// LSTM forecaster: 2-layer encoder (T=256) + 2-layer decoder (HORIZON=24).
// Encoder is software-pipelined across layers: one launch runs L0 step t
// (CTAs 0-127) concurrently with L1 step t-1 (CTAs 128-255) — independent by
// dataflow. Decoder stays one-launch-per-cell (serial through pred).
//
// Per-step GEMM: gates[128 x 4096] = h[128 x 1024] @ W^T (+ optional input).
// CTA c owns hidden cols [8c, 8c+8) across ALL FOUR gates, so the cell update
// is CTA-local. 256 threads, 8 warps = 4 gate-row-groups x 2 batch-halves.
// Thread: 8 gate-rows x 2 batch (float2) with packed fma.rn.f32x2 (scalar
// FFMA-3reg is half-rate on B300; f32x2 restores the full datapath).
// A tile in smem uses an EVEN xor-swizzle: transposed stores conflict-free,
// float2 compute loads 8B-aligned. Double-buffered smem, 1 barrier per chunk.
// ============================================================================

#define B_   128
#define H_   1024
#define T_   256
#define HOR_ 24
#define SSZ  (B_ * H_)

// state: h0[2], c0, h1[2], c1, pred
__device__ __align__(256) float g_state[6 * SSZ + B_];

__device__ __forceinline__ float2 ffma2(float2 a, float2 b, float2 c) {
    unsigned long long ua = *reinterpret_cast<unsigned long long*>(&a);
    unsigned long long ub = *reinterpret_cast<unsigned long long*>(&b);
    unsigned long long uc = *reinterpret_cast<unsigned long long*>(&c);
    unsigned long long ud;
    asm("fma.rn.f32x2 %0, %1, %2, %3;" : "=l"(ud) : "l"(ua), "l"(ub), "l"(uc));
    return *reinterpret_cast<float2*>(&ud);
}

__device__ __forceinline__ float sigmoidf_(float x) {
    return 1.0f / (1.0f + expf(-x));
}

// A-tile swizzle: element (k, b) lives at shA[k*128 + (b ^ XS(k))].
// EVEN by construction (keeps float2 loads 8B-aligned, pairs unswapped).
#define XS(k) ((((k) >> 2) & 15) * 2)

// smem layout (dynamic): shA[2][64*128], shW[2][64*36]
#define SHA_F   (64 * 128)
#define SHW_F   (64 * 36)
#define SMEM_F  (2 * SHA_F + 2 * SHW_F)

// ---------------------------------------------------------------------------
// K=1024 GEMM accumulate: acc[j] += A[b0..b0+1, :] . W[row rg*8+j, :]
// A: [128 x 1024] row-major. W rows r = rg*1024 + cta*8 + j (stride 1024).
// Register-staged LDG pipeline + double-buffered smem (1 barrier / chunk).
// ---------------------------------------------------------------------------
__device__ __forceinline__ void gemm_1024(
    const float* __restrict__ A, const float* __restrict__ W,
    int cta, int rg, int b0,
    float* __restrict__ smem,
    float2 acc[8])
{
    float* shA[2] = { smem,              smem + SHA_F };
    float* shW[2] = { smem + 2 * SHA_F,  smem + 2 * SHA_F + SHW_F };

    const int tid = threadIdx.x;
    // A global-load mapping: lanes 0..15 -> consecutive float4 in k (coalesced)
    const int a_k4 = tid & 15;        // float4 index within 64-k chunk
    const int a_b  = tid >> 4;        // base batch row (+16 per p)
    // W global-load mapping: lane -> row (consecutive), warp -> k-octet
    const int w_rl = tid & 31;
    const int w_k8 = tid >> 5;
    const int w_r  = (w_rl >> 3) * H_ + cta * 8 + (w_rl & 7);

    float4 ra[8];
    float4 rw0, rw1;

#define LOAD_CHUNK(k0)                                                   \
    {                                                                    \
        _Pragma("unroll")                                                \
        for (int p = 0; p < 8; ++p) {                                    \
            int b = a_b + p * 16;                                        \
            ra[p] = *(const float4*)&A[b * H_ + (k0) + 4 * a_k4];        \
        }                                                                \
        rw0 = *(const float4*)&W[w_r * H_ + (k0) + 8 * w_k8];            \
        rw1 = *(const float4*)&W[w_r * H_ + (k0) + 8 * w_k8 + 4];        \
    }

#define STORE_CHUNK(bi)                                                  \
    {                                                                    \
        float* SA = shA[bi];                                             \
        float* SW = shW[bi];                                             \
        _Pragma("unroll")                                                \
        for (int p = 0; p < 8; ++p) {                                    \
            int b = a_b + p * 16;                                        \
            const float* v = (const float*)&ra[p];                       \
            _Pragma("unroll")                                            \
            for (int q = 0; q < 4; ++q) {                                \
                int k = 4 * a_k4 + q;                                    \
                SA[k * 128 + (b ^ (2 * a_k4))] = v[q];                   \
            }                                                            \
        }                                                                \
        {                                                                \
            const float* v = (const float*)&rw0;                         \
            _Pragma("unroll")                                            \
            for (int q = 0; q < 4; ++q)                                  \
                SW[(8 * w_k8 + q) * 36 + w_rl] = v[q];                   \
        }                                                                \
        {                                                                \
            const float* v = (const float*)&rw1;                         \
            _Pragma("unroll")                                            \
            for (int q = 0; q < 4; ++q)                                  \
                SW[(8 * w_k8 + 4 + q) * 36 + w_rl] = v[q];               \
        }                                                                \
    }

#define COMPUTE_CHUNK(bi)                                                \
    {                                                                    \
        const float* SA = shA[bi];                                       \
        const float* SW = shW[bi];                                       \
        _Pragma("unroll")                                                \
        for (int kk = 0; kk < 64; ++kk) {                                \
            float2 a = *(const float2*)&SA[kk * 128 + (b0 ^ XS(kk))];    \
            float4 w0 = *(const float4*)&SW[kk * 36 + 8 * rg];           \
            float4 w1 = *(const float4*)&SW[kk * 36 + 8 * rg + 4];       \
            acc[0] = ffma2(a, make_float2(w0.x, w0.x), acc[0]);          \
            acc[1] = ffma2(a, make_float2(w0.y, w0.y), acc[1]);          \
            acc[2] = ffma2(a, make_float2(w0.z, w0.z), acc[2]);          \
            acc[3] = ffma2(a, make_float2(w0.w, w0.w), acc[3]);          \
            acc[4] = ffma2(a, make_float2(w1.x, w1.x), acc[4]);          \
            acc[5] = ffma2(a, make_float2(w1.y, w1.y), acc[5]);          \
            acc[6] = ffma2(a, make_float2(w1.z, w1.z), acc[6]);          \
            acc[7] = ffma2(a, make_float2(w1.w, w1.w), acc[7]);          \
        }                                                                \
    }

    LOAD_CHUNK(0);
    STORE_CHUNK(0);
    __syncthreads();
    #pragma unroll 1
    for (int c = 1; c < 16; ++c) {
        LOAD_CHUNK(c * 64);           // LDG latency hidden under compute
        COMPUTE_CHUNK((c - 1) & 1);   // read buffer (c-1)&1
        STORE_CHUNK(c & 1);           // write OTHER buffer: no WAR race
        __syncthreads();
    }
    COMPUTE_CHUNK(1);                 // chunk 15 lives in buffer 1

#undef LOAD_CHUNK
#undef STORE_CHUNK
#undef COMPUTE_CHUNK
}

// ---------------------------------------------------------------------------
// LSTM cell body (runs on one 256-thread CTA; cta = logical slice index).
// SMALLK: 0 = none, 8 = encoder L0 x-input (batch stride 2048), 1 = scalar
//         decoder L0 input (pred[b] * Wsmall[r]).
// HASIN:  true -> additional K=1024 input GEMM (Ain @ Win^T).
// ---------------------------------------------------------------------------
template<int SMALLK, bool HASIN>
__device__ __forceinline__ void cell_body(
    const float* __restrict__ Asmall, const float* __restrict__ Wsmall,
    const float* __restrict__ Ain,    const float* __restrict__ Win,
    const float* __restrict__ Hprev,  const float* __restrict__ Whh,
    const float* __restrict__ bias,
    float* __restrict__ Hnext, float* __restrict__ C,
    float* __restrict__ smem, int cta)
{
    const int tid  = threadIdx.x;
    const int lane = tid & 31;
    const int w    = tid >> 5;
    const int rg   = w & 3;               // gate index (warp-constant)
    const int bh   = w >> 2;              // batch half
    const int b0   = 64 * bh + 2 * lane;  // batch pair (b0, b0+1)

    float2 acc[8];

    // init: bias + small-K input contribution
    {
        float ax[8], ay[8];
        if (SMALLK == 8) {
            #pragma unroll
            for (int k = 0; k < 8; ++k) {
                ax[k] = Asmall[b0 * 2048 + k];
                ay[k] = Asmall[(b0 + 1) * 2048 + k];
            }
        } else if (SMALLK == 1) {
            ax[0] = Asmall[b0];
            ay[0] = Asmall[b0 + 1];
        }
        #pragma unroll
        for (int j = 0; j < 8; ++j) {
            int r = rg * H_ + cta * 8 + j;
            float bb = bias[r];
            float vx = bb, vy = bb;
            if (SMALLK == 8) {
                #pragma unroll
                for (int k = 0; k < 8; ++k) {
                    float wk = Wsmall[r * 8 + k];
                    vx += ax[k] * wk;
                    vy += ay[k] * wk;
                }
            } else if (SMALLK == 1) {
                float wk = Wsmall[r];
                vx += ax[0] * wk;
                vy += ay[0] * wk;
            }
            acc[j] = make_float2(vx, vy);
        }
    }

    if (HASIN) gemm_1024(Ain, Win, cta, rg, b0, smem, acc);
    gemm_1024(Hprev, Whh, cta, rg, b0, smem, acc);

    // gate exchange: warp rg owns gate rg's 8 rows; write gates[rl][b] to smem
    __syncthreads();
    float* gbuf = smem;                   // 32 rows x 128 b, stride 130
    #pragma unroll
    for (int j = 0; j < 8; ++j) {
        int rl = 8 * rg + j;
        *(float2*)&gbuf[rl * 130 + b0] = acc[j];   // 130 even, b0 even: aligned
    }
    __syncthreads();

    // cell update: 1024 (b, jj) items, 4 per thread
    #pragma unroll
    for (int p = 0; p < 4; ++p) {
        int idx = tid + p * 256;
        int b = idx & 127, jj = idx >> 7;           // jj in 0..7
        float gi = gbuf[(0 * 8 + jj) * 130 + b];
        float gf = gbuf[(1 * 8 + jj) * 130 + b];
        float gg = gbuf[(2 * 8 + jj) * 130 + b];
        float go = gbuf[(3 * 8 + jj) * 130 + b];
        int col = cta * 8 + jj;
        float c_old = C[b * H_ + col];
        float i_ = sigmoidf_(gi);
        float f_ = sigmoidf_(gf);
        float g_ = tanhf(gg);
        float o_ = sigmoidf_(go);
        float cn = f_ * c_old + i_ * g_;
        float hn = o_ * tanhf(cn);
        C[b * H_ + col] = cn;
        Hnext[b * H_ + col] = hn;
    }
}

// ---------------------------------------------------------------------------
// Fused encoder step: CTAs 0-127 run L0 step t; CTAs 128-255 run L1 step t-1.
// Independent by dataflow: L1[t-1] consumes h0 written by L0[t-1] (previous
// launch). doA=0 skips the L0 half (t==T), doB=0 skips L1 (t==0).
// ---------------------------------------------------------------------------
__global__ void __launch_bounds__(256, 1) enc_fused_k(
    const float* __restrict__ x_t,
    const float* __restrict__ eWih0, const float* __restrict__ eWhh0,
    const float* __restrict__ eb0,
    const float* __restrict__ h0_rd, float* __restrict__ h0_wr,
    float* __restrict__ c0,
    const float* __restrict__ ain1,
    const float* __restrict__ eWih1, const float* __restrict__ eWhh1,
    const float* __restrict__ eb1,
    const float* __restrict__ h1_rd, float* __restrict__ h1_wr,
    float* __restrict__ c1,
    int doA, int doB)
{
    extern __shared__ __align__(16) float smem[];
    if (blockIdx.x < 128) {
        if (!doA) return;
        cell_body<8, false>(x_t, eWih0, nullptr, nullptr,
                            h0_rd, eWhh0, eb0, h0_wr, c0, smem, blockIdx.x);
    } else {
        if (!doB) return;
        cell_body<0, true>(nullptr, nullptr, ain1, eWih1,
                           h1_rd, eWhh1, eb1, h1_wr, c1, smem, blockIdx.x - 128);
    }
}

// ---------------------------------------------------------------------------
// Standalone cell step (decoder).
// ---------------------------------------------------------------------------
template<int SMALLK, bool HASIN>
__global__ void __launch_bounds__(256, 1) lstm_step_k(
    const float* __restrict__ Asmall, const float* __restrict__ Wsmall,
    const float* __restrict__ Ain,    const float* __restrict__ Win,
    const float* __restrict__ Hprev,  const float* __restrict__ Whh,
    const float* __restrict__ bias,
    float* __restrict__ Hnext, float* __restrict__ C)
{
    extern __shared__ __align__(16) float smem[];
    cell_body<SMALLK, HASIN>(Asmall, Wsmall, Ain, Win, Hprev, Whh, bias,
                             Hnext, C, smem, blockIdx.x);
}

// ---------------------------------------------------------------------------
// projection: pred[b] = h1[b,:] . proj_W + proj_b ; writes output column s
// ---------------------------------------------------------------------------
__global__ void proj_kernel(const float* __restrict__ h1,
                            const float* __restrict__ pW,
                            const float* __restrict__ pb,
                            float* __restrict__ out, float* __restrict__ pred,
                            int s)
{
    int b = blockIdx.x;
    int tid = threadIdx.x;                // 128 threads
    float sum = 0.0f;
    for (int k = tid; k < H_; k += 128)
        sum += h1[b * H_ + k] * pW[k];
    __shared__ float red[128];
    red[tid] = sum;
    __syncthreads();
    for (int off = 64; off > 0; off >>= 1) {
        if (tid < off) red[tid] += red[tid + off];
        __syncthreads();
    }
    if (tid == 0) {
        float p = red[0] + pb[0];
        out[b * HOR_ + s] = p;
        pred[b] = p;
    }
}

// ---------------------------------------------------------------------------
// init: zero h0[0], c0, h1[0], c1; pred = x[:, T-1, 0]
// ---------------------------------------------------------------------------
__global__ void init_kernel(const float* __restrict__ x)
{
    int i = blockIdx.x * blockDim.x + threadIdx.x;
    if (i < SSZ) {
        g_state[0 * SSZ + i] = 0.0f;   // h0 parity 0
        g_state[2 * SSZ + i] = 0.0f;   // c0
        g_state[3 * SSZ + i] = 0.0f;   // h1 parity 0
        g_state[5 * SSZ + i] = 0.0f;   // c1
    }
    if (i < B_) g_state[6 * SSZ + i] = x[(i * T_ + (T_ - 1)) * 8 + 0];
}

// ---------------------------------------------------------------------------
extern "C" void kernel_launch(void* const* d_in, const int* in_sizes, int n_in,
                              void* d_out, int out_size)
{
    const float* x     = (const float*)d_in[0];
    const float* eWih0 = (const float*)d_in[1];
    const float* eWhh0 = (const float*)d_in[2];
    const float* eb0   = (const float*)d_in[3];
    const float* eWih1 = (const float*)d_in[4];
    const float* eWhh1 = (const float*)d_in[5];
    const float* eb1   = (const float*)d_in[6];
    const float* dWih0 = (const float*)d_in[7];
    const float* dWhh0 = (const float*)d_in[8];
    const float* db0   = (const float*)d_in[9];
    const float* dWih1 = (const float*)d_in[10];
    const float* dWhh1 = (const float*)d_in[11];
    const float* db1   = (const float*)d_in[12];
    const float* pW    = (const float*)d_in[13];
    const float* pb    = (const float*)d_in[14];
    float* out = (float*)d_out;

    float* base = nullptr;
    cudaGetSymbolAddress((void**)&base, g_state);
    float* h0[2] = { base + 0 * SSZ, base + 1 * SSZ };
    float* c0    =   base + 2 * SSZ;
    float* h1[2] = { base + 3 * SSZ, base + 4 * SSZ };
    float* c1    =   base + 5 * SSZ;
    float* pred  =   base + 6 * SSZ;

    const size_t shbytes = SMEM_F * sizeof(float);   // ~82 KB dynamic smem
    cudaFuncSetAttribute(enc_fused_k,
                         cudaFuncAttributeMaxDynamicSharedMemorySize, (int)shbytes);
    cudaFuncSetAttribute(lstm_step_k<1, false>,
                         cudaFuncAttributeMaxDynamicSharedMemorySize, (int)shbytes);
    cudaFuncSetAttribute(lstm_step_k<0, true>,
                         cudaFuncAttributeMaxDynamicSharedMemorySize, (int)shbytes);

    init_kernel<<<512, 256>>>(x);

    // Encoder, layer-pipelined: launch t runs L0[t] (CTAs 0-127) and L1[t-1]
    // (CTAs 128-255). Parities (p = t&1, pn = (t+1)&1):
    //   L0[t]:   reads h0[p],  writes h0[pn], c0
    //   L1[t-1]: reads h0[p] (= L0[t-1] output) and h1[pn], writes h1[p], c1
    // No intra-launch write/read overlap. t=0 skips L1; t=T skips L0.
    for (int t = 0; t <= T_; ++t) {
        int p = t & 1, pn = (t + 1) & 1;
        const float* xt = (t < T_) ? (x + t * 8) : x;   // unused when doA=0
        enc_fused_k<<<256, 256, shbytes>>>(
            xt, eWih0, eWhh0, eb0, h0[p], h0[pn], c0,
            h0[p], eWih1, eWhh1, eb1, h1[pn], h1[p], c1,
            (t < T_) ? 1 : 0, (t > 0) ? 1 : 0);
    }
    // After t=T_ (=256): L1[255] wrote h1[0]; L0[255] wrote h0[0].
    // Decoder continues at parity 0.

    dim3 gs(128), bs(256);
    for (int s = 0; s < HOR_; ++s) {
        int p = s & 1, pn = (s + 1) & 1;
        lstm_step_k<1, false><<<gs, bs, shbytes>>>(
            pred, dWih0, nullptr, nullptr, h0[p], dWhh0, db0, h0[pn], c0);
        lstm_step_k<0, true><<<gs, bs, shbytes>>>(
            nullptr, nullptr, h0[pn], dWih1, h1[p], dWhh1, db1, h1[pn], c1);
        proj_kernel<<<128, 128>>>(h1[pn], pW, pb, out, pred, s);
    }
}

// round 16
// speedup vs baseline: 1.5567x; 1.5567x over previous
#include <cuda_runtime.h>
#include <cuda_bf16.h>
#include <math.h>

// ============================================================================
// LSTM forecaster: 2-layer encoder (T=256, layer-pipelined) + 2-layer decoder.
// Redesign from first ncu profile (regs=255, occ=12.2%, fma=21.8%):
//  * h and c kept TRANSPOSED in global (hT[col][b]) -> A tiles are contiguous
//    32KB blocks, loaded by cp.async (no reg staging, no STS transpose).
//  * Weights pre-transposed once per launch into g_wprep[mat][cta][chunk][kk][rl]
//    -> W tiles are contiguous 8KB cp.async copies.
//  * FFMA2 vectorized over adjacent gate-row pairs (natural register pairs
//    from LDS.128), batch value broadcast (<=4 MOVs/kk).
//  * __launch_bounds__(256,2): 2 CTAs/SM -> 256-CTA encoder launch single-wave.
// ============================================================================

#define B_   128
#define H_   1024
#define T_   256
#define HOR_ 24
#define SSZ  (B_ * H_)

// state: h0T[2], c0T, h1T[2], c1T, pred   (all [col][b] layout, col*128+b)
__device__ __align__(256) float g_state[6 * SSZ + B_];

// prepped weights: 6 mats x 128 cta x 16 chunk x 64 kk x 32 rl
#define WP_PER_MAT (128 * 16 * 64 * 32)      // 4,194,304 floats
#define WP_PER_CTA (16 * 64 * 32)            // 32,768 floats
__device__ __align__(256) float g_wprep[6 * WP_PER_MAT];   // ~100.7 MB

__device__ __forceinline__ float2 ffma2(float2 a, float2 b, float2 c) {
    unsigned long long ua = *reinterpret_cast<unsigned long long*>(&a);
    unsigned long long ub = *reinterpret_cast<unsigned long long*>(&b);
    unsigned long long uc = *reinterpret_cast<unsigned long long*>(&c);
    unsigned long long ud;
    asm("fma.rn.f32x2 %0, %1, %2, %3;" : "=l"(ud) : "l"(ua), "l"(ub), "l"(uc));
    return *reinterpret_cast<float2*>(&ud);
}

__device__ __forceinline__ float sigmoidf_(float x) {
    return 1.0f / (1.0f + expf(-x));
}

__device__ __forceinline__ void cpa16(unsigned dst, const void* src) {
    asm volatile("cp.async.cg.shared.global [%0], [%1], 16;"
                 :: "r"(dst), "l"(src) : "memory");
}
#define CPA_COMMIT() asm volatile("cp.async.commit_group;" ::: "memory")
#define CPA_WAIT1()  asm volatile("cp.async.wait_group 1;" ::: "memory")
#define CPA_WAIT0()  asm volatile("cp.async.wait_group 0;" ::: "memory")

// smem (floats): smA[2][8192], smW[2][2048]  -> 20480 floats = 80 KB
#define SMA_F 8192
#define SMW_F 2048
#define SMW_BASE (2 * SMA_F)
#define SMEM_F (2 * SMA_F + 2 * SMW_F)

// ---------------------------------------------------------------------------
// K=1024 GEMM accumulate using prepped operands.
// AT:  [1024 col][128 b] contiguous; chunk c = AT + c*8192 (32 KB block).
// Wp:  per-cta base; chunk c = Wp + c*2048 ([kk][32 rl], rows 128B).
// acc[jp][bb]: row pair (8rg+2jp, +1) x batch (b0+bb).
// Double-buffered cp.async pipeline, 2 barriers per chunk.
// ---------------------------------------------------------------------------
__device__ __forceinline__ void gemm_async(
    const float* __restrict__ AT, const float* __restrict__ Wp,
    int rg, int b0,
    float* __restrict__ smem, unsigned smem_u32,
    float2 acc[4][2])
{
    const int tid = threadIdx.x;

#define ISSUE(c, bi)                                                        \
    {                                                                       \
        unsigned dA = smem_u32 + (unsigned)((bi) * SMA_F) * 4u;             \
        const float* sA = AT + (c) * 8192;                                  \
        _Pragma("unroll")                                                   \
        for (int p = 0; p < 8; ++p) {                                       \
            int id = tid + p * 256;                                         \
            cpa16(dA + id * 16u, sA + id * 4);                              \
        }                                                                   \
        unsigned dW = smem_u32 + (unsigned)(SMW_BASE + (bi) * SMW_F) * 4u;  \
        const float* sW = Wp + (c) * 2048;                                  \
        _Pragma("unroll")                                                   \
        for (int p = 0; p < 2; ++p) {                                       \
            int id = tid + p * 256;                                         \
            cpa16(dW + id * 16u, sW + id * 4);                              \
        }                                                                   \
    }

#define COMPUTE(bi)                                                         \
    {                                                                       \
        const float* SA = smem + (bi) * SMA_F;                              \
        const float* SW = smem + SMW_BASE + (bi) * SMW_F;                   \
        _Pragma("unroll 16")                                                \
        for (int kk = 0; kk < 64; ++kk) {                                   \
            float2 a2 = *(const float2*)&SA[kk * 128 + b0];                 \
            float4 w0 = *(const float4*)&SW[kk * 32 + 8 * rg];              \
            float4 w1 = *(const float4*)&SW[kk * 32 + 8 * rg + 4];          \
            float2 aa0 = make_float2(a2.x, a2.x);                           \
            float2 aa1 = make_float2(a2.y, a2.y);                           \
            acc[0][0] = ffma2(make_float2(w0.x, w0.y), aa0, acc[0][0]);     \
            acc[0][1] = ffma2(make_float2(w0.x, w0.y), aa1, acc[0][1]);     \
            acc[1][0] = ffma2(make_float2(w0.z, w0.w), aa0, acc[1][0]);     \
            acc[1][1] = ffma2(make_float2(w0.z, w0.w), aa1, acc[1][1]);     \
            acc[2][0] = ffma2(make_float2(w1.x, w1.y), aa0, acc[2][0]);     \
            acc[2][1] = ffma2(make_float2(w1.x, w1.y), aa1, acc[2][1]);     \
            acc[3][0] = ffma2(make_float2(w1.z, w1.w), aa0, acc[3][0]);     \
            acc[3][1] = ffma2(make_float2(w1.z, w1.w), aa1, acc[3][1]);     \
        }                                                                   \
    }

    ISSUE(0, 0);
    CPA_COMMIT();
    #pragma unroll 1
    for (int c = 0; c < 16; ++c) {
        if (c < 15) {
            ISSUE(c + 1, (c + 1) & 1);
            CPA_COMMIT();
            CPA_WAIT1();              // chunk c's copies complete
        } else {
            CPA_WAIT0();
        }
        __syncthreads();              // all threads' data visible
        COMPUTE(c & 1);
        __syncthreads();              // buffer reuse safe before next issue
    }

#undef ISSUE
#undef COMPUTE
}

// ---------------------------------------------------------------------------
// LSTM cell body. SMALLK: 0 none, 8 encoder-L0 x (batch stride 2048),
// 1 scalar decoder-L0 input. HASIN -> extra K=1024 input GEMM.
// All h/c tensors in [col][b] layout (col*128 + b).
// ---------------------------------------------------------------------------
template<int SMALLK, bool HASIN>
__device__ __forceinline__ void cell_body(
    const float* __restrict__ Asmall, const float* __restrict__ Wsmall,
    const float* __restrict__ AinT,   const float* __restrict__ WinP,
    const float* __restrict__ HprevT, const float* __restrict__ WhhP,
    const float* __restrict__ bias,
    float* __restrict__ HnextT, float* __restrict__ CT,
    float* __restrict__ smem, unsigned smem_u32, int cta)
{
    const int tid  = threadIdx.x;
    const int lane = tid & 31;
    const int w    = tid >> 5;
    const int rg   = w & 3;               // gate (warp-constant)
    const int bh   = w >> 2;              // batch half
    const int b0   = 64 * bh + 2 * lane;  // batch pair

    float2 acc[4][2];

    // init: bias + small-K input
    #pragma unroll
    for (int jp = 0; jp < 4; ++jp) {
        int r0 = rg * H_ + cta * 8 + 2 * jp;
        float bl = bias[r0], bhv = bias[r0 + 1];
        #pragma unroll
        for (int bb = 0; bb < 2; ++bb) {
            float vl = bl, vh = bhv;
            if (SMALLK == 8) {
                #pragma unroll
                for (int k = 0; k < 8; ++k) {
                    float xv = Asmall[(b0 + bb) * 2048 + k];
                    vl += xv * Wsmall[r0 * 8 + k];
                    vh += xv * Wsmall[(r0 + 1) * 8 + k];
                }
            } else if (SMALLK == 1) {
                float xv = Asmall[b0 + bb];
                vl += xv * Wsmall[r0];
                vh += xv * Wsmall[r0 + 1];
            }
            acc[jp][bb] = make_float2(vl, vh);
        }
    }

    if (HASIN) gemm_async(AinT, WinP + cta * WP_PER_CTA, rg, b0, smem, smem_u32, acc);
    gemm_async(HprevT, WhhP + cta * WP_PER_CTA, rg, b0, smem, smem_u32, acc);

    // gate exchange: gbuf[b][rl], stride 34 (reuses smA[0])
    __syncthreads();
    float* gbuf = smem;
    #pragma unroll
    for (int jp = 0; jp < 4; ++jp) {
        #pragma unroll
        for (int bb = 0; bb < 2; ++bb) {
            *(float2*)&gbuf[(b0 + bb) * 34 + 8 * rg + 2 * jp] = acc[jp][bb];
        }
    }
    __syncthreads();

    // cell update: 1024 (b, jj) items, 4 per thread; coalesced hT/cT writes
    #pragma unroll
    for (int p = 0; p < 4; ++p) {
        int idx = tid + p * 256;
        int b = idx & 127, jj = idx >> 7;
        float gi = gbuf[b * 34 + 0 * 8 + jj];
        float gf = gbuf[b * 34 + 1 * 8 + jj];
        float gg = gbuf[b * 34 + 2 * 8 + jj];
        float go = gbuf[b * 34 + 3 * 8 + jj];
        int ca = (cta * 8 + jj) * 128 + b;
        float c_old = CT[ca];
        float i_ = sigmoidf_(gi);
        float f_ = sigmoidf_(gf);
        float g_ = tanhf(gg);
        float o_ = sigmoidf_(go);
        float cn = f_ * c_old + i_ * g_;
        float hn = o_ * tanhf(cn);
        CT[ca] = cn;
        HnextT[ca] = hn;
    }
}

// ---------------------------------------------------------------------------
// Fused encoder step: CTAs 0-127 = L0[t]; 128-255 = L1[t-1] (independent).
// ---------------------------------------------------------------------------
__global__ void __launch_bounds__(256, 2) enc_fused_k(
    const float* __restrict__ x_t,
    const float* __restrict__ eWih0, const float* __restrict__ eWhh0P,
    const float* __restrict__ eb0,
    const float* __restrict__ h0_rd, float* __restrict__ h0_wr,
    float* __restrict__ c0,
    const float* __restrict__ ain1,
    const float* __restrict__ eWih1P, const float* __restrict__ eWhh1P,
    const float* __restrict__ eb1,
    const float* __restrict__ h1_rd, float* __restrict__ h1_wr,
    float* __restrict__ c1,
    int doA, int doB)
{
    extern __shared__ __align__(16) float smem[];
    unsigned su = (unsigned)__cvta_generic_to_shared(smem);
    if (blockIdx.x < 128) {
        if (!doA) return;
        cell_body<8, false>(x_t, eWih0, nullptr, nullptr,
                            h0_rd, eWhh0P, eb0, h0_wr, c0, smem, su, blockIdx.x);
    } else {
        if (!doB) return;
        cell_body<0, true>(nullptr, nullptr, ain1, eWih1P,
                           h1_rd, eWhh1P, eb1, h1_wr, c1, smem, su,
                           blockIdx.x - 128);
    }
}

template<int SMALLK, bool HASIN>
__global__ void __launch_bounds__(256, 2) lstm_step_k(
    const float* __restrict__ Asmall, const float* __restrict__ Wsmall,
    const float* __restrict__ AinT,   const float* __restrict__ WinP,
    const float* __restrict__ HprevT, const float* __restrict__ WhhP,
    const float* __restrict__ bias,
    float* __restrict__ HnextT, float* __restrict__ CT)
{
    extern __shared__ __align__(16) float smem[];
    unsigned su = (unsigned)__cvta_generic_to_shared(smem);
    cell_body<SMALLK, HASIN>(Asmall, Wsmall, AinT, WinP, HprevT, WhhP, bias,
                             HnextT, CT, smem, su, blockIdx.x);
}

// ---------------------------------------------------------------------------
// weight prep: g_wprep[m][cta][ch][kk][rl] = W_m[(rl>>3)*1024 + cta*8 + (rl&7)]
//                                               [ch*64 + kk]
// dst-linear mapping: coalesced writes; reads L1-deduplicated within a block.
// ---------------------------------------------------------------------------
__global__ void prep_kernel(
    const float* __restrict__ w0, const float* __restrict__ w1,
    const float* __restrict__ w2, const float* __restrict__ w3,
    const float* __restrict__ w4, const float* __restrict__ w5)
{
    int m = blockIdx.y;
    const float* src = (m == 0) ? w0 : (m == 1) ? w1 : (m == 2) ? w2
                     : (m == 3) ? w3 : (m == 4) ? w4 : w5;
    int id = blockIdx.x * 256 + threadIdx.x;      // < 4,194,304
    int rl  = id & 31;
    int kk  = (id >> 5) & 63;
    int ch  = (id >> 11) & 15;
    int cta = id >> 15;
    int r = (rl >> 3) * 1024 + cta * 8 + (rl & 7);
    int k = ch * 64 + kk;
    g_wprep[m * WP_PER_MAT + id] = src[r * 1024 + k];
}

// ---------------------------------------------------------------------------
// projection from h1T: pred[b] = sum_col h1T[col*128+b]*pW[col] + pb
// ---------------------------------------------------------------------------
__global__ void proj_kernel(const float* __restrict__ h1T,
                            const float* __restrict__ pW,
                            const float* __restrict__ pb,
                            float* __restrict__ out, float* __restrict__ pred,
                            int s)
{
    int b = blockIdx.x;
    int tid = threadIdx.x;                // 128 threads
    float sum = 0.0f;
    for (int col = tid; col < H_; col += 128)
        sum += h1T[col * 128 + b] * pW[col];
    __shared__ float red[128];
    red[tid] = sum;
    __syncthreads();
    for (int off = 64; off > 0; off >>= 1) {
        if (tid < off) red[tid] += red[tid + off];
        __syncthreads();
    }
    if (tid == 0) {
        float p = red[0] + pb[0];
        out[b * HOR_ + s] = p;
        pred[b] = p;
    }
}

__global__ void init_kernel(const float* __restrict__ x)
{
    int i = blockIdx.x * blockDim.x + threadIdx.x;
    if (i < SSZ) {
        g_state[0 * SSZ + i] = 0.0f;   // h0T parity 0
        g_state[2 * SSZ + i] = 0.0f;   // c0T
        g_state[3 * SSZ + i] = 0.0f;   // h1T parity 0
        g_state[5 * SSZ + i] = 0.0f;   // c1T
    }
    if (i < B_) g_state[6 * SSZ + i] = x[(i * T_ + (T_ - 1)) * 8 + 0];
}

// ---------------------------------------------------------------------------
extern "C" void kernel_launch(void* const* d_in, const int* in_sizes, int n_in,
                              void* d_out, int out_size)
{
    const float* x     = (const float*)d_in[0];
    const float* eWih0 = (const float*)d_in[1];
    const float* eWhh0 = (const float*)d_in[2];
    const float* eb0   = (const float*)d_in[3];
    const float* eWih1 = (const float*)d_in[4];
    const float* eWhh1 = (const float*)d_in[5];
    const float* eb1   = (const float*)d_in[6];
    const float* dWih0 = (const float*)d_in[7];
    const float* dWhh0 = (const float*)d_in[8];
    const float* db0   = (const float*)d_in[9];
    const float* dWih1 = (const float*)d_in[10];
    const float* dWhh1 = (const float*)d_in[11];
    const float* db1   = (const float*)d_in[12];
    const float* pW    = (const float*)d_in[13];
    const float* pb    = (const float*)d_in[14];
    float* out = (float*)d_out;

    float* base = nullptr;
    cudaGetSymbolAddress((void**)&base, g_state);
    float* h0[2] = { base + 0 * SSZ, base + 1 * SSZ };
    float* c0    =   base + 2 * SSZ;
    float* h1[2] = { base + 3 * SSZ, base + 4 * SSZ };
    float* c1    =   base + 5 * SSZ;
    float* pred  =   base + 6 * SSZ;

    float* wp = nullptr;
    cudaGetSymbolAddress((void**)&wp, g_wprep);
    // mats: 0 eWhh0, 1 eWih1, 2 eWhh1, 3 dWhh0, 4 dWih1, 5 dWhh1
    float* eWhh0P = wp + 0 * WP_PER_MAT;
    float* eWih1P = wp + 1 * WP_PER_MAT;
    float* eWhh1P = wp + 2 * WP_PER_MAT;
    float* dWhh0P = wp + 3 * WP_PER_MAT;
    float* dWih1P = wp + 4 * WP_PER_MAT;
    float* dWhh1P = wp + 5 * WP_PER_MAT;

    const size_t shbytes = SMEM_F * sizeof(float);   // 80 KB dynamic smem
    cudaFuncSetAttribute(enc_fused_k,
                         cudaFuncAttributeMaxDynamicSharedMemorySize, (int)shbytes);
    cudaFuncSetAttribute(lstm_step_k<1, false>,
                         cudaFuncAttributeMaxDynamicSharedMemorySize, (int)shbytes);
    cudaFuncSetAttribute(lstm_step_k<0, true>,
                         cudaFuncAttributeMaxDynamicSharedMemorySize, (int)shbytes);

    prep_kernel<<<dim3(WP_PER_MAT / 256, 6), 256>>>(
        eWhh0, eWih1, eWhh1, dWhh0, dWih1, dWhh1);
    init_kernel<<<512, 256>>>(x);

    // Encoder, layer-pipelined (parities p = t&1, pn = (t+1)&1):
    //   L0[t]:   reads h0[p],  writes h0[pn], c0
    //   L1[t-1]: reads h0[p] (= L0[t-1] output) and h1[pn], writes h1[p], c1
    for (int t = 0; t <= T_; ++t) {
        int p = t & 1, pn = (t + 1) & 1;
        const float* xt = (t < T_) ? (x + t * 8) : x;   // unused when doA=0
        enc_fused_k<<<256, 256, shbytes>>>(
            xt, eWih0, eWhh0P, eb0, h0[p], h0[pn], c0,
            h0[p], eWih1P, eWhh1P, eb1, h1[pn], h1[p], c1,
            (t < T_) ? 1 : 0, (t > 0) ? 1 : 0);
    }
    // Encoder finals land at parity 0; decoder continues there.

    dim3 gs(128), bs(256);
    for (int s = 0; s < HOR_; ++s) {
        int p = s & 1, pn = (s + 1) & 1;
        lstm_step_k<1, false><<<gs, bs, shbytes>>>(
            pred, dWih0, nullptr, nullptr, h0[p], dWhh0P, db0, h0[pn], c0);
        lstm_step_k<0, true><<<gs, bs, shbytes>>>(
            nullptr, nullptr, h0[pn], dWih1P, h1[p], dWhh1P, db1, h1[pn], c1);
        proj_kernel<<<128, 128>>>(h1[pn], pW, pb, out, pred, s);
    }
}